// round 9
// baseline (speedup 1.0000x reference)
#include <cuda_runtime.h>
#include <cuda_bf16.h>
#include <cstdint>
#include <math.h>

#define NROWS 8192
#define D     128
#define INV_T (1.0f / 0.07f)
#define SCALE_LOG2 (INV_T * 1.44269504089f)
#define CLIP_LOG2  (10.0f * 1.44269504089f)

#define NT       64
#define NTILES   2080          // NT*(NT+1)/2
#define GRID     148           // 1 persistent CTA per SM
#define STAGES   4
#define CHUNKS   4
#define ROWPITCH 80            // 64B data + 16B pad (LDSM conflict-free)
#define TILEB    (128 * ROWPITCH)          // 10240
#define STAGEB   (2 * TILEB)               // 20480
#define SMEM_DYN_BYTES (STAGES * STAGEB)   // 81920

// ---------------- device scratch -------------------------------------------
__device__ __nv_bfloat16 g_f16[NROWS * D];
__device__ float g_pos[NROWS];
__device__ float g_neg[NROWS];
__device__ int   g_lab[NROWS];

// ---------------- helpers ---------------------------------------------------
__device__ __forceinline__ uint32_t smem_u32(const void* p) {
    return (uint32_t)__cvta_generic_to_shared(p);
}
__device__ __forceinline__ void cpasync16(uint32_t s, const void* g) {
    asm volatile("cp.async.cg.shared.global [%0], [%1], 16;" :: "r"(s), "l"(g));
}
__device__ __forceinline__ void cp_commit() {
    asm volatile("cp.async.commit_group;" ::: "memory");
}
template <int N>
__device__ __forceinline__ void cp_wait() {
    asm volatile("cp.async.wait_group %0;" :: "n"(N) : "memory");
}
__device__ __forceinline__ void ldmx4(uint32_t* r, uint32_t addr) {
    asm volatile("ldmatrix.sync.aligned.m8n8.x4.shared.b16 {%0,%1,%2,%3}, [%4];"
                 : "=r"(r[0]), "=r"(r[1]), "=r"(r[2]), "=r"(r[3]) : "r"(addr));
}
__device__ __forceinline__ void mma16816(float* c, const uint32_t* a, uint32_t b0, uint32_t b1) {
    asm volatile(
        "mma.sync.aligned.m16n8k16.row.col.f32.bf16.bf16.f32 "
        "{%0,%1,%2,%3}, {%4,%5,%6,%7}, {%8,%9}, {%0,%1,%2,%3};"
        : "+f"(c[0]), "+f"(c[1]), "+f"(c[2]), "+f"(c[3])
        : "r"(a[0]), "r"(a[1]), "r"(a[2]), "r"(a[3]), "r"(b0), "r"(b1));
}
__device__ __forceinline__ float ex2(float x) {
    float r;
    asm("ex2.approx.f32 %0, %1;" : "=f"(r) : "f"(x));
    return r;
}
__device__ __forceinline__ void decode_tile(int ti, int& i, int& j) {
    i = (int)floorf((129.0f - sqrtf(129.0f * 129.0f - 8.0f * (float)ti)) * 0.5f);
    while (i > 0 && ti < i * NT - i * (i - 1) / 2) --i;
    while (ti >= (i + 1) * NT - (i + 1) * i / 2) ++i;
    j = i + (ti - (i * NT - i * (i - 1) / 2));
}

// ---------------------------------------------------------------------------
// Kernel 1: warp-per-row normalize -> bf16; labels; zero accumulators.
// ---------------------------------------------------------------------------
__global__ void __launch_bounds__(256) normalize_kernel(
    const float* __restrict__ feat,
    const int*   __restrict__ lab32)
{
    const int warp = threadIdx.x >> 5;
    const int lane = threadIdx.x & 31;
    const int row  = blockIdx.x * 8 + warp;

    float4 v = *(const float4*)&feat[row * D + lane * 4];
    float ss = v.x * v.x + v.y * v.y + v.z * v.z + v.w * v.w;
    #pragma unroll
    for (int o = 16; o > 0; o >>= 1) ss += __shfl_xor_sync(0xffffffffu, ss, o);
    float inv = 1.0f / fmaxf(sqrtf(ss), 1e-8f);

    float f[4] = { v.x * inv, v.y * inv, v.z * inv, v.w * inv };
    ushort h[4];
    #pragma unroll
    for (int k = 0; k < 4; k++)
        h[k] = __bfloat16_as_ushort(__float2bfloat16_rn(f[k]));
    *(uint2*)&((ushort*)g_f16)[row * D + lane * 4] =
        make_uint2(h[0] | (uint32_t)h[1] << 16, h[2] | (uint32_t)h[3] << 16);

    if (lane == 0) {
        g_pos[row] = 0.0f;
        g_neg[row] = 0.0f;
        bool is64 = true;
        #pragma unroll 8
        for (int i = 0; i < 32; i++)
            if (lab32[2 * i + 1] != 0) { is64 = false; break; }
        g_lab[row] = is64 ? lab32[2 * row] : lab32[row];
    }
}

// ---------------------------------------------------------------------------
// Kernel 2: persistent tiles; epilogue of tile t software-pipelined into the
// MMA chunk loop of tile t+1 (MUFU/FMA hides in the HMMA shadow).
// ---------------------------------------------------------------------------
__device__ __forceinline__ void load_chunk(uint32_t stageBase, int chunk,
                                           int aRowBase, int bRowBase, int tid)
{
    const int col = chunk * 32;
    #pragma unroll
    for (int it = 0; it < 2; it++) {
        int idx = tid + it * 256;
        int r   = idx >> 2;
        int c4  = idx & 3;
        uint32_t s = stageBase + r * ROWPITCH + c4 * 16;
        cpasync16(s,         (const char*)&g_f16[(aRowBase + r) * D + col] + c4 * 16);
        cpasync16(s + TILEB, (const char*)&g_f16[(bRowBase + r) * D + col] + c4 * 16);
    }
}

__global__ void __launch_bounds__(256, 1) sim_mma_kernel()
{
    extern __shared__ char dsm[];
    __shared__ int labA[2][128];
    __shared__ int labB[2][128];

    const uint32_t smBase = smem_u32(dsm);
    const int tid  = threadIdx.x;
    const int warp = tid >> 5;
    const int lane = tid & 31;
    const int warpRow = warp >> 1;
    const int warpCol = warp & 1;
    const int g   = lane >> 2;
    const int tig = lane & 3;

    uint32_t aOff[2];
    #pragma unroll
    for (int mi = 0; mi < 2; mi++)
        aOff[mi] = (uint32_t)((warpRow * 32 + mi * 16 + (lane & 15)) * ROWPITCH
                              + ((lane >> 4) * 16));
    uint32_t bOff[4];
    #pragma unroll
    for (int nt = 0; nt < 4; nt++)
        bOff[nt] = (uint32_t)((warpCol * 64 + nt * 16 + (lane & 7) + ((lane & 16) ? 8 : 0))
                              * ROWPITCH + ((lane & 8) ? 16 : 0));

    int ti = blockIdx.x;
    int i, j;
    decode_tile(ti, i, j);
    int aR = i * 128, bR = j * 128;

    // ---- pipelined-epilogue state (tile t-1) ----
    float epi[2][8][4];
    float colP[16], colN[16];
    float rp[2][2], rn[2][2];
    int  aR_e = 0, bR_e = 0, lb_e = 0;
    bool diag_e = false;
    bool pend = false;

    auto epi_quarter = [&](int q) {
        if (!pend) return;
        #pragma unroll
        for (int n8 = 2 * q; n8 < 2 * q + 2; n8++) {
            #pragma unroll
            for (int mi = 0; mi < 2; mi++) {
                #pragma unroll
                for (int h = 0; h < 2; h++) {
                    const int rT = warpRow * 32 + mi * 16 + h * 8 + g;
                    const int lrow = labA[lb_e][rT];
                    #pragma unroll
                    for (int e = 0; e < 2; e++) {
                        const int cT = warpCol * 64 + n8 * 8 + 2 * tig + e;
                        float v = epi[mi][n8][h * 2 + e];
                        float s = fminf(fmaxf(v * SCALE_LOG2, -CLIP_LOG2), CLIP_LOG2);
                        float exv = ex2(s);
                        if (diag_e) exv = (rT == cT) ? 0.0f : exv;
                        bool m = (lrow == labB[lb_e][cT]);
                        rn[mi][h] += exv;
                        rp[mi][h] += m ? exv : 0.0f;
                        if (!diag_e) {
                            colN[n8 * 2 + e] += exv;
                            colP[n8 * 2 + e] += m ? exv : 0.0f;
                        }
                    }
                }
            }
        }
    };

    auto epi_finish = [&]() {
        if (!pend) return;
        #pragma unroll
        for (int mi = 0; mi < 2; mi++) {
            #pragma unroll
            for (int h = 0; h < 2; h++) {
                float p = rp[mi][h], n = rn[mi][h];
                #pragma unroll
                for (int o = 1; o < 4; o <<= 1) {
                    p += __shfl_xor_sync(0xffffffffu, p, o);
                    n += __shfl_xor_sync(0xffffffffu, n, o);
                }
                if (tig == 0) {
                    const int rT = warpRow * 32 + mi * 16 + h * 8 + g;
                    atomicAdd(&g_pos[aR_e + rT], p);
                    atomicAdd(&g_neg[aR_e + rT], n);
                }
            }
        }
        if (!diag_e) {
            #pragma unroll
            for (int x = 0; x < 16; x++) {
                #pragma unroll
                for (int o = 4; o < 32; o <<= 1) {
                    colP[x] += __shfl_xor_sync(0xffffffffu, colP[x], o);
                    colN[x] += __shfl_xor_sync(0xffffffffu, colN[x], o);
                }
            }
            if (g == 0) {
                #pragma unroll
                for (int x = 0; x < 16; x++) {
                    const int cT = warpCol * 64 + (x >> 1) * 8 + 2 * tig + (x & 1);
                    atomicAdd(&g_pos[bR_e + cT], colP[x]);
                    atomicAdd(&g_neg[bR_e + cT], colN[x]);
                }
            }
        }
    };

    // prologue: chunks 0..2 of first tile
    #pragma unroll
    for (int s = 0; s < 3; s++) {
        load_chunk(smBase + s * STAGEB, s, aR, bR, tid);
        cp_commit();
    }

    int tlocal = 0;
    #pragma unroll 1
    while (true) {
        const bool diag = (aR == bR);
        const int ti_next = ti + GRID;
        const bool hasNext = (ti_next < NTILES);
        int aRn = 0, bRn = 0;
        if (hasNext) {
            int in, jn;
            decode_tile(ti_next, in, jn);
            aRn = in * 128; bRn = jn * 128;
        }
        const int lb = tlocal & 1;

        float acc[2][8][4];
        #pragma unroll
        for (int a = 0; a < 2; a++)
            #pragma unroll
            for (int b = 0; b < 8; b++)
                #pragma unroll
                for (int k = 0; k < 4; k++) acc[a][b][k] = 0.0f;

        #pragma unroll
        for (int c = 0; c < CHUNKS; c++) {
            cp_wait<2>();
            __syncthreads();

            if (c == 0 && tid < 128) {
                labA[lb][tid] = g_lab[aR + tid];
                labB[lb][tid] = g_lab[bR + tid];
            }

            if (c == 0)
                load_chunk(smBase + 3 * STAGEB, 3, aR, bR, tid);
            else if (hasNext)
                load_chunk(smBase + (c - 1) * STAGEB, c - 1, aRn, bRn, tid);
            cp_commit();

            const uint32_t aS = smBase + c * STAGEB;
            const uint32_t bS = aS + TILEB;

            #pragma unroll
            for (int k16 = 0; k16 < 2; k16++) {
                uint32_t a[2][4];
                ldmx4(a[0], aS + aOff[0] + k16 * 32);
                ldmx4(a[1], aS + aOff[1] + k16 * 32);
                uint32_t b[4][4];
                #pragma unroll
                for (int nt = 0; nt < 4; nt++)
                    ldmx4(b[nt], bS + bOff[nt] + k16 * 32);
                #pragma unroll
                for (int mi = 0; mi < 2; mi++)
                    #pragma unroll
                    for (int n8 = 0; n8 < 8; n8++) {
                        const uint32_t* bf = b[n8 >> 1];
                        if (n8 & 1) mma16816(acc[mi][n8], a[mi], bf[2], bf[3]);
                        else        mma16816(acc[mi][n8], a[mi], bf[0], bf[1]);
                    }
            }

            // interleaved quarter of the PREVIOUS tile's epilogue
            epi_quarter(c);
        }

        // finish previous tile's reductions; stage this tile's acc
        epi_finish();

        #pragma unroll
        for (int a = 0; a < 2; a++)
            #pragma unroll
            for (int b = 0; b < 8; b++)
                #pragma unroll
                for (int k = 0; k < 4; k++) epi[a][b][k] = acc[a][b][k];
        #pragma unroll
        for (int x = 0; x < 16; x++) { colP[x] = 0.0f; colN[x] = 0.0f; }
        #pragma unroll
        for (int a = 0; a < 2; a++)
            #pragma unroll
            for (int h = 0; h < 2; h++) { rp[a][h] = 0.0f; rn[a][h] = 0.0f; }
        aR_e = aR; bR_e = bR; diag_e = diag; lb_e = lb;
        pend = true;

        if (!hasNext) break;
        ti = ti_next; aR = aRn; bR = bRn; ++tlocal;
    }

    // flush last tile's epilogue
    #pragma unroll
    for (int q = 0; q < 4; q++) epi_quarter(q);
    epi_finish();
}

// ---------------------------------------------------------------------------
// Kernel 3: final loss reduction.
// ---------------------------------------------------------------------------
__global__ void __launch_bounds__(1024) loss_kernel(float* __restrict__ out)
{
    int t = threadIdx.x;
    float s = 0.0f;
    for (int idx = t; idx < NROWS; idx += 1024) {
        float p = fmaxf(g_pos[idx], 1e-8f);
        float n = fmaxf(g_neg[idx], 1e-8f);
        s += logf(n) - logf(p);
    }
    __shared__ float red[1024];
    red[t] = s;
    __syncthreads();
    #pragma unroll
    for (int o = 512; o > 0; o >>= 1) {
        if (t < o) red[t] += red[t + o];
        __syncthreads();
    }
    if (t == 0) out[0] = red[0] * (1.0f / (float)NROWS);
}

// ---------------------------------------------------------------------------
extern "C" void kernel_launch(void* const* d_in, const int* in_sizes, int n_in,
                              void* d_out, int out_size)
{
    const float* feat  = (const float*)d_in[0];
    const int*   lab32 = (const int*)d_in[1];
    float*       out   = (float*)d_out;

    static bool attr_set = false;
    if (!attr_set) {
        cudaFuncSetAttribute(sim_mma_kernel, cudaFuncAttributeMaxDynamicSharedMemorySize,
                             SMEM_DYN_BYTES);
        attr_set = true;
    }

    normalize_kernel<<<NROWS / 8, 256>>>(feat, lab32);
    sim_mma_kernel<<<GRID, 256, SMEM_DYN_BYTES>>>();
    loss_kernel<<<1, 1024>>>(out);
}

// round 10
// speedup vs baseline: 1.3664x; 1.3664x over previous
#include <cuda_runtime.h>
#include <cuda_bf16.h>
#include <cstdint>
#include <math.h>

#define NROWS 8192
#define D     128
#define INV_T (1.0f / 0.07f)
#define SCALE_LOG2 (INV_T * 1.44269504089f)
#define CLIP_LOG2  (10.0f * 1.44269504089f)

#define NT       64
#define NTILES   2080          // NT*(NT+1)/2
#define GRID     296           // 2 persistent CTAs per SM
#define ROWPITCH 80            // 64B data + 16B pad (LDSM conflict-free)
#define CHUNKB   (128 * ROWPITCH)          // 10240 per 32-col chunk
#define A_BYTES  (4 * CHUNKB)              // resident A tile (K=128)
#define B_BYTES  (4 * CHUNKB)              // 4-slot B ring
#define SMEM_DYN_BYTES (A_BYTES + B_BYTES) // 81920

// ---------------- device scratch -------------------------------------------
__device__ __nv_bfloat16 g_f16[NROWS * D];
__device__ float g_pos[NROWS];
__device__ float g_neg[NROWS];
__device__ int   g_lab[NROWS];

// ---------------- helpers ---------------------------------------------------
__device__ __forceinline__ uint32_t smem_u32(const void* p) {
    return (uint32_t)__cvta_generic_to_shared(p);
}
__device__ __forceinline__ void cpasync16(uint32_t s, const void* g) {
    asm volatile("cp.async.cg.shared.global [%0], [%1], 16;" :: "r"(s), "l"(g));
}
__device__ __forceinline__ void cp_commit() {
    asm volatile("cp.async.commit_group;" ::: "memory");
}
template <int N>
__device__ __forceinline__ void cp_wait() {
    asm volatile("cp.async.wait_group %0;" :: "n"(N) : "memory");
}
__device__ __forceinline__ void ldmx4(uint32_t* r, uint32_t addr) {
    asm volatile("ldmatrix.sync.aligned.m8n8.x4.shared.b16 {%0,%1,%2,%3}, [%4];"
                 : "=r"(r[0]), "=r"(r[1]), "=r"(r[2]), "=r"(r[3]) : "r"(addr));
}
__device__ __forceinline__ void mma16816(float* c, const uint32_t* a, uint32_t b0, uint32_t b1) {
    asm volatile(
        "mma.sync.aligned.m16n8k16.row.col.f32.bf16.bf16.f32 "
        "{%0,%1,%2,%3}, {%4,%5,%6,%7}, {%8,%9}, {%0,%1,%2,%3};"
        : "+f"(c[0]), "+f"(c[1]), "+f"(c[2]), "+f"(c[3])
        : "r"(a[0]), "r"(a[1]), "r"(a[2]), "r"(a[3]), "r"(b0), "r"(b1));
}
__device__ __forceinline__ float ex2(float x) {
    float r;
    asm("ex2.approx.f32 %0, %1;" : "=f"(r) : "f"(x));
    return r;
}
__device__ __forceinline__ void decode_tile(int ti, int& i, int& j) {
    i = (int)floorf((129.0f - sqrtf(129.0f * 129.0f - 8.0f * (float)ti)) * 0.5f);
    while (i > 0 && ti < i * NT - i * (i - 1) / 2) --i;
    while (ti >= (i + 1) * NT - (i + 1) * i / 2) ++i;
    j = i + (ti - (i * NT - i * (i - 1) / 2));
}

// ---------------------------------------------------------------------------
// Kernel 1: warp-per-row normalize -> bf16; labels; zero accumulators.
// ---------------------------------------------------------------------------
__global__ void __launch_bounds__(256) normalize_kernel(
    const float* __restrict__ feat,
    const int*   __restrict__ lab32)
{
    const int warp = threadIdx.x >> 5;
    const int lane = threadIdx.x & 31;
    const int row  = blockIdx.x * 8 + warp;

    float4 v = *(const float4*)&feat[row * D + lane * 4];
    float ss = v.x * v.x + v.y * v.y + v.z * v.z + v.w * v.w;
    #pragma unroll
    for (int o = 16; o > 0; o >>= 1) ss += __shfl_xor_sync(0xffffffffu, ss, o);
    float inv = 1.0f / fmaxf(sqrtf(ss), 1e-8f);

    float f[4] = { v.x * inv, v.y * inv, v.z * inv, v.w * inv };
    ushort h[4];
    #pragma unroll
    for (int k = 0; k < 4; k++)
        h[k] = __bfloat16_as_ushort(__float2bfloat16_rn(f[k]));
    *(uint2*)&((ushort*)g_f16)[row * D + lane * 4] =
        make_uint2(h[0] | (uint32_t)h[1] << 16, h[2] | (uint32_t)h[3] << 16);

    if (lane == 0) {
        g_pos[row] = 0.0f;
        g_neg[row] = 0.0f;
        bool is64 = true;
        #pragma unroll 8
        for (int i = 0; i < 32; i++)
            if (lab32[2 * i + 1] != 0) { is64 = false; break; }
        g_lab[row] = is64 ? lab32[2 * row] : lab32[row];
    }
}

// ---------------------------------------------------------------------------
// Kernel 2: persistent CTAs over contiguous triangular tile runs. A tile
// resident in smem per row-block run; B streams through a 4-slot cp.async
// ring rolling across tile boundaries.
// ---------------------------------------------------------------------------
__device__ __forceinline__ void load_A(uint32_t Abase, int aR, int tid) {
    #pragma unroll
    for (int ch = 0; ch < 4; ch++) {
        const int col = ch * 32;
        #pragma unroll
        for (int it = 0; it < 2; it++) {
            int idx = tid + it * 256;
            int r   = idx >> 2;
            int c4  = idx & 3;
            cpasync16(Abase + ch * CHUNKB + r * ROWPITCH + c4 * 16,
                      (const char*)&g_f16[(aR + r) * D + col] + c4 * 16);
        }
    }
}
__device__ __forceinline__ void load_B_chunk(uint32_t Bbase, int slot, int chunk,
                                             int bR, int tid) {
    const int col = chunk * 32;
    #pragma unroll
    for (int it = 0; it < 2; it++) {
        int idx = tid + it * 256;
        int r   = idx >> 2;
        int c4  = idx & 3;
        cpasync16(Bbase + slot * CHUNKB + r * ROWPITCH + c4 * 16,
                  (const char*)&g_f16[(bR + r) * D + col] + c4 * 16);
    }
}

__global__ void __launch_bounds__(256, 2) sim_mma_kernel()
{
    extern __shared__ char dsm[];
    __shared__ int labA[2][128];
    __shared__ int labB[2][128];

    const uint32_t smBase = smem_u32(dsm);
    const uint32_t Abase  = smBase;
    const uint32_t Bbase  = smBase + A_BYTES;
    const int tid  = threadIdx.x;
    const int warp = tid >> 5;
    const int lane = tid & 31;
    const int warpRow = warp >> 1;
    const int warpCol = warp & 1;
    const int g   = lane >> 2;
    const int tig = lane & 3;

    uint32_t aOff[2];
    #pragma unroll
    for (int mi = 0; mi < 2; mi++)
        aOff[mi] = (uint32_t)((warpRow * 32 + mi * 16 + (lane & 15)) * ROWPITCH
                              + ((lane >> 4) * 16));
    uint32_t bOff[4];
    #pragma unroll
    for (int nt = 0; nt < 4; nt++)
        bOff[nt] = (uint32_t)((warpCol * 64 + nt * 16 + (lane & 7) + ((lane & 16) ? 8 : 0))
                              * ROWPITCH + ((lane & 8) ? 16 : 0));

    // contiguous run: 2080 = 296*7 + 8
    const int cta   = blockIdx.x;
    const int cnt   = 7 + (cta < 8 ? 1 : 0);
    const int start = cta * 7 + min(cta, 8);

    int i, j;
    decode_tile(start, i, j);
    int aR = i * 128, bR = j * 128;

    // prologue: resident A (1 group), then B chunks 0..2 (3 groups)
    load_A(Abase, aR, tid);
    cp_commit();
    #pragma unroll
    for (int s = 0; s < 3; s++) {
        load_B_chunk(Bbase, s, s, bR, tid);
        cp_commit();
    }

    bool needDrain = false;   // first tile: wait<2> drains A+B0 (4 groups pending)

    #pragma unroll 1
    for (int t = 0; t < cnt; t++) {
        const bool diag = (i == j);
        const bool hasNext = (t + 1 < cnt);
        int i_n = i, j_n = j + 1;
        if (j == NT - 1) { i_n = i + 1; j_n = i_n; }
        const bool iChange = hasNext && (i_n != i);
        const int bRn = j_n * 128;
        const int lb = t & 1;

        float acc[2][8][4];
        #pragma unroll
        for (int a = 0; a < 2; a++)
            #pragma unroll
            for (int b = 0; b < 8; b++)
                #pragma unroll
                for (int k = 0; k < 4; k++) acc[a][b][k] = 0.0f;

        #pragma unroll
        for (int c = 0; c < 4; c++) {
            if (c == 0 && needDrain) cp_wait<0>();
            else                     cp_wait<2>();
            __syncthreads();

            if (c == 0 && tid < 128) {
                labA[lb][tid] = g_lab[aR + tid];
                labB[lb][tid] = g_lab[bR + tid];
            }

            if (c == 0)
                load_B_chunk(Bbase, 3, 3, bR, tid);
            else if (hasNext)
                load_B_chunk(Bbase, c - 1, c - 1, bRn, tid);
            cp_commit();

            const uint32_t aS = Abase + c * CHUNKB;
            const uint32_t bS = Bbase + c * CHUNKB;

            #pragma unroll
            for (int k16 = 0; k16 < 2; k16++) {
                uint32_t a[2][4];
                ldmx4(a[0], aS + aOff[0] + k16 * 32);
                ldmx4(a[1], aS + aOff[1] + k16 * 32);
                uint32_t b[4][4];
                #pragma unroll
                for (int nt = 0; nt < 4; nt++)
                    ldmx4(b[nt], bS + bOff[nt] + k16 * 32);
                #pragma unroll
                for (int mi = 0; mi < 2; mi++)
                    #pragma unroll
                    for (int n8 = 0; n8 < 8; n8++) {
                        const uint32_t* bf = b[n8 >> 1];
                        if (n8 & 1) mma16816(acc[mi][n8], a[mi], bf[2], bf[3]);
                        else        mma16816(acc[mi][n8], a[mi], bf[0], bf[1]);
                    }
            }
        }

        // on row-block change: prefetch new resident A during the epilogue
        if (iChange) {
            __syncthreads();              // all warps done reading old A
            load_A(Abase, i_n * 128, tid);
            cp_commit();
            needDrain = true;
        } else {
            needDrain = false;
        }

        // ---------------- fused epilogue (row + column sums) ----------------
        float colPos[16], colNeg[16];
        #pragma unroll
        for (int x = 0; x < 16; x++) { colPos[x] = 0.0f; colNeg[x] = 0.0f; }

        #pragma unroll
        for (int mi = 0; mi < 2; mi++) {
            #pragma unroll
            for (int h = 0; h < 2; h++) {
                const int rT   = warpRow * 32 + mi * 16 + h * 8 + g;
                const int lrow = labA[lb][rT];
                float rowPos = 0.0f, rowNeg = 0.0f;
                #pragma unroll
                for (int n8 = 0; n8 < 8; n8++) {
                    #pragma unroll
                    for (int e = 0; e < 2; e++) {
                        const int cT = warpCol * 64 + n8 * 8 + 2 * tig + e;
                        float v = acc[mi][n8][h * 2 + e];
                        float s = fminf(fmaxf(v * SCALE_LOG2, -CLIP_LOG2), CLIP_LOG2);
                        float exv = ex2(s);
                        if (diag) exv = (rT == cT) ? 0.0f : exv;
                        bool m = (lrow == labB[lb][cT]);
                        rowNeg += exv;
                        rowPos += m ? exv : 0.0f;
                        if (!diag) {
                            colNeg[n8 * 2 + e] += exv;
                            colPos[n8 * 2 + e] += m ? exv : 0.0f;
                        }
                    }
                }
                #pragma unroll
                for (int o = 1; o < 4; o <<= 1) {
                    rowPos += __shfl_xor_sync(0xffffffffu, rowPos, o);
                    rowNeg += __shfl_xor_sync(0xffffffffu, rowNeg, o);
                }
                if (tig == 0) {
                    atomicAdd(&g_pos[aR + rT], rowPos);
                    atomicAdd(&g_neg[aR + rT], rowNeg);
                }
            }
        }

        if (!diag) {
            #pragma unroll
            for (int x = 0; x < 16; x++) {
                #pragma unroll
                for (int o = 4; o < 32; o <<= 1) {
                    colPos[x] += __shfl_xor_sync(0xffffffffu, colPos[x], o);
                    colNeg[x] += __shfl_xor_sync(0xffffffffu, colNeg[x], o);
                }
            }
            if (g == 0) {
                #pragma unroll
                for (int x = 0; x < 16; x++) {
                    const int cT = warpCol * 64 + (x >> 1) * 8 + 2 * tig + (x & 1);
                    atomicAdd(&g_pos[bR + cT], colPos[x]);
                    atomicAdd(&g_neg[bR + cT], colNeg[x]);
                }
            }
        }

        i = i_n; j = j_n; aR = i * 128; bR = j * 128;
    }
}

// ---------------------------------------------------------------------------
// Kernel 3: final loss reduction.
// ---------------------------------------------------------------------------
__global__ void __launch_bounds__(1024) loss_kernel(float* __restrict__ out)
{
    int t = threadIdx.x;
    float s = 0.0f;
    for (int idx = t; idx < NROWS; idx += 1024) {
        float p = fmaxf(g_pos[idx], 1e-8f);
        float n = fmaxf(g_neg[idx], 1e-8f);
        s += logf(n) - logf(p);
    }
    __shared__ float red[1024];
    red[t] = s;
    __syncthreads();
    #pragma unroll
    for (int o = 512; o > 0; o >>= 1) {
        if (t < o) red[t] += red[t + o];
        __syncthreads();
    }
    if (t == 0) out[0] = red[0] * (1.0f / (float)NROWS);
}

// ---------------------------------------------------------------------------
extern "C" void kernel_launch(void* const* d_in, const int* in_sizes, int n_in,
                              void* d_out, int out_size)
{
    const float* feat  = (const float*)d_in[0];
    const int*   lab32 = (const int*)d_in[1];
    float*       out   = (float*)d_out;

    static bool attr_set = false;
    if (!attr_set) {
        cudaFuncSetAttribute(sim_mma_kernel, cudaFuncAttributeMaxDynamicSharedMemorySize,
                             SMEM_DYN_BYTES);
        attr_set = true;
    }

    normalize_kernel<<<NROWS / 8, 256>>>(feat, lab32);
    sim_mma_kernel<<<GRID, 256, SMEM_DYN_BYTES>>>();
    loss_kernel<<<1, 1024>>>(out);
}

// round 11
// speedup vs baseline: 1.4126x; 1.0338x over previous
#include <cuda_runtime.h>
#include <cuda_bf16.h>
#include <cstdint>
#include <math.h>

#define NROWS 8192
#define D     128
// alpha = sqrt((1/0.07) * log2(e)); alpha^2 = 20.6099291556
#define ALPHA  4.539816f
#define CLIP2  14.4269504089f   // 10 * log2(e)

#define NT       64
#define NTILES   2080          // NT*(NT+1)/2
#define GRID     296           // 2 persistent CTAs per SM
#define ROWPITCH 80            // 64B data + 16B pad (LDSM conflict-free)
#define CHUNKB   (128 * ROWPITCH)          // 10240 per 32-col chunk
#define A_BYTES  (4 * CHUNKB)
#define B_BYTES  (4 * CHUNKB)
#define SMEM_DYN_BYTES (A_BYTES + B_BYTES) // 81920

// ---------------- device scratch -------------------------------------------
__device__ __nv_bfloat16 g_f16[NROWS * D];   // alpha-prescaled normalized rows
__device__ float g_pos[NROWS];
__device__ float g_neg[NROWS];
__device__ int   g_lab[NROWS];

// ---------------- helpers ---------------------------------------------------
__device__ __forceinline__ uint32_t smem_u32(const void* p) {
    return (uint32_t)__cvta_generic_to_shared(p);
}
__device__ __forceinline__ void cpasync16(uint32_t s, const void* g) {
    asm volatile("cp.async.cg.shared.global [%0], [%1], 16;" :: "r"(s), "l"(g));
}
__device__ __forceinline__ void cp_commit() {
    asm volatile("cp.async.commit_group;" ::: "memory");
}
template <int N>
__device__ __forceinline__ void cp_wait() {
    asm volatile("cp.async.wait_group %0;" :: "n"(N) : "memory");
}
__device__ __forceinline__ void ldmx4(uint32_t* r, uint32_t addr) {
    asm volatile("ldmatrix.sync.aligned.m8n8.x4.shared.b16 {%0,%1,%2,%3}, [%4];"
                 : "=r"(r[0]), "=r"(r[1]), "=r"(r[2]), "=r"(r[3]) : "r"(addr));
}
__device__ __forceinline__ void mma16816(float* c, const uint32_t* a, uint32_t b0, uint32_t b1) {
    asm volatile(
        "mma.sync.aligned.m16n8k16.row.col.f32.bf16.bf16.f32 "
        "{%0,%1,%2,%3}, {%4,%5,%6,%7}, {%8,%9}, {%0,%1,%2,%3};"
        : "+f"(c[0]), "+f"(c[1]), "+f"(c[2]), "+f"(c[3])
        : "r"(a[0]), "r"(a[1]), "r"(a[2]), "r"(a[3]), "r"(b0), "r"(b1));
}
__device__ __forceinline__ float ex2(float x) {
    float r;
    asm("ex2.approx.f32 %0, %1;" : "=f"(r) : "f"(x));
    return r;
}
__device__ __forceinline__ float lg2(float x) {
    float r;
    asm("lg2.approx.f32 %0, %1;" : "=f"(r) : "f"(x));
    return r;
}
__device__ __forceinline__ void decode_tile(int ti, int& i, int& j) {
    i = (int)floorf((129.0f - sqrtf(129.0f * 129.0f - 8.0f * (float)ti)) * 0.5f);
    while (i > 0 && ti < i * NT - i * (i - 1) / 2) --i;
    while (ti >= (i + 1) * NT - (i + 1) * i / 2) ++i;
    j = i + (ti - (i * NT - i * (i - 1) / 2));
}

// ---------------------------------------------------------------------------
// Kernel 1: 2 rows per warp (double MLP), normalize -> alpha-prescaled bf16.
// ---------------------------------------------------------------------------
__global__ void __launch_bounds__(256) normalize_kernel(
    const float* __restrict__ feat,
    const int*   __restrict__ lab32)
{
    const int warp = threadIdx.x >> 5;
    const int lane = threadIdx.x & 31;
    const int row0 = blockIdx.x * 16 + warp * 2;
    const int row1 = row0 + 1;

    float4 v0 = *(const float4*)&feat[row0 * D + lane * 4];
    float4 v1 = *(const float4*)&feat[row1 * D + lane * 4];

    float ss0 = v0.x * v0.x + v0.y * v0.y + v0.z * v0.z + v0.w * v0.w;
    float ss1 = v1.x * v1.x + v1.y * v1.y + v1.z * v1.z + v1.w * v1.w;
    #pragma unroll
    for (int o = 16; o > 0; o >>= 1) {
        ss0 += __shfl_xor_sync(0xffffffffu, ss0, o);
        ss1 += __shfl_xor_sync(0xffffffffu, ss1, o);
    }
    float inv0 = ALPHA / fmaxf(sqrtf(ss0), 1e-8f);
    float inv1 = ALPHA / fmaxf(sqrtf(ss1), 1e-8f);

    ushort h0[4], h1[4];
    h0[0] = __bfloat16_as_ushort(__float2bfloat16_rn(v0.x * inv0));
    h0[1] = __bfloat16_as_ushort(__float2bfloat16_rn(v0.y * inv0));
    h0[2] = __bfloat16_as_ushort(__float2bfloat16_rn(v0.z * inv0));
    h0[3] = __bfloat16_as_ushort(__float2bfloat16_rn(v0.w * inv0));
    h1[0] = __bfloat16_as_ushort(__float2bfloat16_rn(v1.x * inv1));
    h1[1] = __bfloat16_as_ushort(__float2bfloat16_rn(v1.y * inv1));
    h1[2] = __bfloat16_as_ushort(__float2bfloat16_rn(v1.z * inv1));
    h1[3] = __bfloat16_as_ushort(__float2bfloat16_rn(v1.w * inv1));
    ushort* a16 = (ushort*)g_f16;
    *(uint2*)&a16[row0 * D + lane * 4] =
        make_uint2(h0[0] | (uint32_t)h0[1] << 16, h0[2] | (uint32_t)h0[3] << 16);
    *(uint2*)&a16[row1 * D + lane * 4] =
        make_uint2(h1[0] | (uint32_t)h1[1] << 16, h1[2] | (uint32_t)h1[3] << 16);

    if (lane == 0) {
        g_pos[row0] = 0.0f; g_neg[row0] = 0.0f;
        g_pos[row1] = 0.0f; g_neg[row1] = 0.0f;
        bool is64 = true;
        #pragma unroll 8
        for (int i = 0; i < 32; i++)
            if (lab32[2 * i + 1] != 0) { is64 = false; break; }
        g_lab[row0] = is64 ? lab32[2 * row0] : lab32[row0];
        g_lab[row1] = is64 ? lab32[2 * row1] : lab32[row1];
    }
}

// ---------------------------------------------------------------------------
// Kernel 2: persistent CTAs over contiguous triangular tile runs; resident A,
// B streamed through 4-slot cp.async ring. MMA output is directly the log2-
// domain exponent (alpha prescale), so epilogue = min + ex2 + adds.
// ---------------------------------------------------------------------------
__device__ __forceinline__ void load_A(uint32_t Abase, int aR, int tid) {
    #pragma unroll
    for (int ch = 0; ch < 4; ch++) {
        const int col = ch * 32;
        #pragma unroll
        for (int it = 0; it < 2; it++) {
            int idx = tid + it * 256;
            int r   = idx >> 2;
            int c4  = idx & 3;
            cpasync16(Abase + ch * CHUNKB + r * ROWPITCH + c4 * 16,
                      (const char*)&g_f16[(aR + r) * D + col] + c4 * 16);
        }
    }
}
__device__ __forceinline__ void load_B_chunk(uint32_t Bbase, int slot, int chunk,
                                             int bR, int tid) {
    const int col = chunk * 32;
    #pragma unroll
    for (int it = 0; it < 2; it++) {
        int idx = tid + it * 256;
        int r   = idx >> 2;
        int c4  = idx & 3;
        cpasync16(Bbase + slot * CHUNKB + r * ROWPITCH + c4 * 16,
                  (const char*)&g_f16[(bR + r) * D + col] + c4 * 16);
    }
}

__global__ void __launch_bounds__(256, 2) sim_mma_kernel()
{
    extern __shared__ char dsm[];
    __shared__ int labA[2][128];
    __shared__ int labB[2][128];

    const uint32_t smBase = smem_u32(dsm);
    const uint32_t Abase  = smBase;
    const uint32_t Bbase  = smBase + A_BYTES;
    const int tid  = threadIdx.x;
    const int warp = tid >> 5;
    const int lane = tid & 31;
    const int warpRow = warp >> 1;
    const int warpCol = warp & 1;
    const int g   = lane >> 2;
    const int tig = lane & 3;

    uint32_t aOff[2];
    #pragma unroll
    for (int mi = 0; mi < 2; mi++)
        aOff[mi] = (uint32_t)((warpRow * 32 + mi * 16 + (lane & 15)) * ROWPITCH
                              + ((lane >> 4) * 16));
    uint32_t bOff[4];
    #pragma unroll
    for (int nt = 0; nt < 4; nt++)
        bOff[nt] = (uint32_t)((warpCol * 64 + nt * 16 + (lane & 7) + ((lane & 16) ? 8 : 0))
                              * ROWPITCH + ((lane & 8) ? 16 : 0));

    // contiguous run: 2080 = 296*7 + 8
    const int cta   = blockIdx.x;
    const int cnt   = 7 + (cta < 8 ? 1 : 0);
    const int start = cta * 7 + min(cta, 8);

    int i, j;
    decode_tile(start, i, j);
    int aR = i * 128, bR = j * 128;

    load_A(Abase, aR, tid);
    cp_commit();
    #pragma unroll
    for (int s = 0; s < 3; s++) {
        load_B_chunk(Bbase, s, s, bR, tid);
        cp_commit();
    }

    bool needDrain = false;

    #pragma unroll 1
    for (int t = 0; t < cnt; t++) {
        const bool diag = (i == j);
        const bool hasNext = (t + 1 < cnt);
        int i_n = i, j_n = j + 1;
        if (j == NT - 1) { i_n = i + 1; j_n = i_n; }
        const bool iChange = hasNext && (i_n != i);
        const int bRn = j_n * 128;
        const int lb = t & 1;

        float acc[2][8][4];
        #pragma unroll
        for (int a = 0; a < 2; a++)
            #pragma unroll
            for (int b = 0; b < 8; b++)
                #pragma unroll
                for (int k = 0; k < 4; k++) acc[a][b][k] = 0.0f;

        #pragma unroll
        for (int c = 0; c < 4; c++) {
            if (c == 0 && needDrain) cp_wait<0>();
            else                     cp_wait<2>();
            __syncthreads();

            if (c == 0 && tid < 128) {
                labA[lb][tid] = g_lab[aR + tid];
                labB[lb][tid] = g_lab[bR + tid];
            }

            if (c == 0)
                load_B_chunk(Bbase, 3, 3, bR, tid);
            else if (hasNext)
                load_B_chunk(Bbase, c - 1, c - 1, bRn, tid);
            cp_commit();

            const uint32_t aS = Abase + c * CHUNKB;
            const uint32_t bS = Bbase + c * CHUNKB;

            #pragma unroll
            for (int k16 = 0; k16 < 2; k16++) {
                uint32_t a[2][4];
                ldmx4(a[0], aS + aOff[0] + k16 * 32);
                ldmx4(a[1], aS + aOff[1] + k16 * 32);
                uint32_t b[4][4];
                #pragma unroll
                for (int nt = 0; nt < 4; nt++)
                    ldmx4(b[nt], bS + bOff[nt] + k16 * 32);
                #pragma unroll
                for (int mi = 0; mi < 2; mi++)
                    #pragma unroll
                    for (int n8 = 0; n8 < 8; n8++) {
                        const uint32_t* bf = b[n8 >> 1];
                        if (n8 & 1) mma16816(acc[mi][n8], a[mi], bf[2], bf[3]);
                        else        mma16816(acc[mi][n8], a[mi], bf[0], bf[1]);
                    }
            }
        }

        if (iChange) {
            __syncthreads();
            load_A(Abase, i_n * 128, tid);
            cp_commit();
            needDrain = true;
        } else {
            needDrain = false;
        }

        // ---------------- fused epilogue (row + column sums) ----------------
        float colPos[16], colNeg[16];
        #pragma unroll
        for (int x = 0; x < 16; x++) { colPos[x] = 0.0f; colNeg[x] = 0.0f; }

        #pragma unroll
        for (int mi = 0; mi < 2; mi++) {
            #pragma unroll
            for (int h = 0; h < 2; h++) {
                const int rT   = warpRow * 32 + mi * 16 + h * 8 + g;
                const int lrow = labA[lb][rT];
                float rowPos = 0.0f, rowNeg = 0.0f;
                #pragma unroll
                for (int n8 = 0; n8 < 8; n8++) {
                    #pragma unroll
                    for (int e = 0; e < 2; e++) {
                        const int cT = warpCol * 64 + n8 * 8 + 2 * tig + e;
                        // acc IS the log2-domain exponent (alpha prescale)
                        float exv = ex2(fminf(acc[mi][n8][h * 2 + e], CLIP2));
                        if (diag) exv = (rT == cT) ? 0.0f : exv;
                        bool m = (lrow == labB[lb][cT]);
                        rowNeg += exv;
                        rowPos += m ? exv : 0.0f;
                        if (!diag) {
                            colNeg[n8 * 2 + e] += exv;
                            colPos[n8 * 2 + e] += m ? exv : 0.0f;
                        }
                    }
                }
                #pragma unroll
                for (int o = 1; o < 4; o <<= 1) {
                    rowPos += __shfl_xor_sync(0xffffffffu, rowPos, o);
                    rowNeg += __shfl_xor_sync(0xffffffffu, rowNeg, o);
                }
                if (tig == 0) {
                    atomicAdd(&g_pos[aR + rT], rowPos);
                    atomicAdd(&g_neg[aR + rT], rowNeg);
                }
            }
        }

        if (!diag) {
            #pragma unroll
            for (int x = 0; x < 16; x++) {
                #pragma unroll
                for (int o = 4; o < 32; o <<= 1) {
                    colPos[x] += __shfl_xor_sync(0xffffffffu, colPos[x], o);
                    colNeg[x] += __shfl_xor_sync(0xffffffffu, colNeg[x], o);
                }
            }
            if (g == 0) {
                #pragma unroll
                for (int x = 0; x < 16; x++) {
                    const int cT = warpCol * 64 + (x >> 1) * 8 + 2 * tig + (x & 1);
                    atomicAdd(&g_pos[bR + cT], colPos[x]);
                    atomicAdd(&g_neg[bR + cT], colNeg[x]);
                }
            }
        }

        i = i_n; j = j_n; aR = i * 128; bR = j * 128;
    }
}

// ---------------------------------------------------------------------------
// Kernel 3: final loss reduction (lg2.approx).
// ---------------------------------------------------------------------------
__global__ void __launch_bounds__(1024) loss_kernel(float* __restrict__ out)
{
    int t = threadIdx.x;
    float s = 0.0f;
    for (int idx = t; idx < NROWS; idx += 1024) {
        float p = fmaxf(g_pos[idx], 1e-8f);
        float n = fmaxf(g_neg[idx], 1e-8f);
        s += lg2(n) - lg2(p);
    }
    __shared__ float red[1024];
    red[t] = s;
    __syncthreads();
    #pragma unroll
    for (int o = 512; o > 0; o >>= 1) {
        if (t < o) red[t] += red[t + o];
        __syncthreads();
    }
    if (t == 0) out[0] = red[0] * (0.69314718056f / (float)NROWS);
}

// ---------------------------------------------------------------------------
extern "C" void kernel_launch(void* const* d_in, const int* in_sizes, int n_in,
                              void* d_out, int out_size)
{
    const float* feat  = (const float*)d_in[0];
    const int*   lab32 = (const int*)d_in[1];
    float*       out   = (float*)d_out;

    static bool attr_set = false;
    if (!attr_set) {
        cudaFuncSetAttribute(sim_mma_kernel, cudaFuncAttributeMaxDynamicSharedMemorySize,
                             SMEM_DYN_BYTES);
        attr_set = true;
    }

    normalize_kernel<<<NROWS / 16, 256>>>(feat, lab32);
    sim_mma_kernel<<<GRID, 256, SMEM_DYN_BYTES>>>();
    loss_kernel<<<1, 1024>>>(out);
}

// round 12
// speedup vs baseline: 1.4252x; 1.0090x over previous
#include <cuda_runtime.h>
#include <cuda_bf16.h>
#include <cstdint>
#include <math.h>

#define NROWS 8192
#define D     128
// alpha = sqrt((1/0.07) * log2(e))
#define ALPHA  4.539816f
#define CLIP2  14.4269504089f   // 10 * log2(e)

#define NT       64
#define NTILES   2080          // NT*(NT+1)/2
#define GRID     296           // 2 persistent CTAs per SM
#define ROWPITCH 80            // 64B data + 16B pad (LDSM conflict-free)
#define CHUNKB   (128 * ROWPITCH)          // 10240 per 32-col chunk
#define A_BYTES  (4 * CHUNKB)
#define B_BYTES  (4 * CHUNKB)
#define SMEM_DYN_BYTES (A_BYTES + B_BYTES) // 81920

// ---------------- device scratch -------------------------------------------
__device__ __nv_bfloat16 g_f16[NROWS * D];   // alpha-prescaled normalized rows
__device__ float g_pos[NROWS];
__device__ float g_neg[NROWS];
__device__ int   g_lab[NROWS];

// ---------------- helpers ---------------------------------------------------
__device__ __forceinline__ uint32_t smem_u32(const void* p) {
    return (uint32_t)__cvta_generic_to_shared(p);
}
__device__ __forceinline__ void cpasync16(uint32_t s, const void* g) {
    asm volatile("cp.async.cg.shared.global [%0], [%1], 16;" :: "r"(s), "l"(g));
}
__device__ __forceinline__ void cp_commit() {
    asm volatile("cp.async.commit_group;" ::: "memory");
}
template <int N>
__device__ __forceinline__ void cp_wait() {
    asm volatile("cp.async.wait_group %0;" :: "n"(N) : "memory");
}
__device__ __forceinline__ void ldmx4(uint32_t* r, uint32_t addr) {
    asm volatile("ldmatrix.sync.aligned.m8n8.x4.shared.b16 {%0,%1,%2,%3}, [%4];"
                 : "=r"(r[0]), "=r"(r[1]), "=r"(r[2]), "=r"(r[3]) : "r"(addr));
}
__device__ __forceinline__ void mma16816(float* c, const uint32_t* a, uint32_t b0, uint32_t b1) {
    asm volatile(
        "mma.sync.aligned.m16n8k16.row.col.f32.bf16.bf16.f32 "
        "{%0,%1,%2,%3}, {%4,%5,%6,%7}, {%8,%9}, {%0,%1,%2,%3};"
        : "+f"(c[0]), "+f"(c[1]), "+f"(c[2]), "+f"(c[3])
        : "r"(a[0]), "r"(a[1]), "r"(a[2]), "r"(a[3]), "r"(b0), "r"(b1));
}
__device__ __forceinline__ float ex2(float x) {
    float r;
    asm("ex2.approx.f32 %0, %1;" : "=f"(r) : "f"(x));
    return r;
}
__device__ __forceinline__ float lg2(float x) {
    float r;
    asm("lg2.approx.f32 %0, %1;" : "=f"(r) : "f"(x));
    return r;
}
__device__ __forceinline__ void decode_tile(int ti, int& i, int& j) {
    i = (int)floorf((129.0f - sqrtf(129.0f * 129.0f - 8.0f * (float)ti)) * 0.5f);
    while (i > 0 && ti < i * NT - i * (i - 1) / 2) --i;
    while (ti >= (i + 1) * NT - (i + 1) * i / 2) ++i;
    j = i + (ti - (i * NT - i * (i - 1) / 2));
}

// ---------------------------------------------------------------------------
// Kernel 1: warp-per-row normalize -> alpha-prescaled bf16 (high occupancy).
// ---------------------------------------------------------------------------
__global__ void __launch_bounds__(256) normalize_kernel(
    const float* __restrict__ feat,
    const int*   __restrict__ lab32)
{
    const int warp = threadIdx.x >> 5;
    const int lane = threadIdx.x & 31;
    const int row  = blockIdx.x * 8 + warp;

    float4 v = *(const float4*)&feat[row * D + lane * 4];
    float ss = v.x * v.x + v.y * v.y + v.z * v.z + v.w * v.w;
    #pragma unroll
    for (int o = 16; o > 0; o >>= 1) ss += __shfl_xor_sync(0xffffffffu, ss, o);
    float inv = ALPHA / fmaxf(sqrtf(ss), 1e-8f);

    ushort h[4];
    h[0] = __bfloat16_as_ushort(__float2bfloat16_rn(v.x * inv));
    h[1] = __bfloat16_as_ushort(__float2bfloat16_rn(v.y * inv));
    h[2] = __bfloat16_as_ushort(__float2bfloat16_rn(v.z * inv));
    h[3] = __bfloat16_as_ushort(__float2bfloat16_rn(v.w * inv));
    *(uint2*)&((ushort*)g_f16)[row * D + lane * 4] =
        make_uint2(h[0] | (uint32_t)h[1] << 16, h[2] | (uint32_t)h[3] << 16);

    if (lane == 0) {
        g_pos[row] = 0.0f;
        g_neg[row] = 0.0f;
        bool is64 = true;
        #pragma unroll 8
        for (int i = 0; i < 32; i++)
            if (lab32[2 * i + 1] != 0) { is64 = false; break; }
        g_lab[row] = is64 ? lab32[2 * row] : lab32[row];
    }
}

// ---------------------------------------------------------------------------
// Kernel 2: persistent CTAs over contiguous triangular tile runs; resident A;
// B streamed in 2-chunk pairs (one wait+sync per pair, prefetch 1 pair ahead).
// ---------------------------------------------------------------------------
__device__ __forceinline__ void load_A(uint32_t Abase, int aR, int tid) {
    #pragma unroll
    for (int ch = 0; ch < 4; ch++) {
        const int col = ch * 32;
        #pragma unroll
        for (int it = 0; it < 2; it++) {
            int idx = tid + it * 256;
            int r   = idx >> 2;
            int c4  = idx & 3;
            cpasync16(Abase + ch * CHUNKB + r * ROWPITCH + c4 * 16,
                      (const char*)&g_f16[(aR + r) * D + col] + c4 * 16);
        }
    }
}
// load B chunks [c0, c0+1] into slots [c0, c0+1]
__device__ __forceinline__ void load_B_pair(uint32_t Bbase, int c0, int bR, int tid) {
    #pragma unroll
    for (int cc = 0; cc < 2; cc++) {
        const int ch  = c0 + cc;
        const int col = ch * 32;
        #pragma unroll
        for (int it = 0; it < 2; it++) {
            int idx = tid + it * 256;
            int r   = idx >> 2;
            int c4  = idx & 3;
            cpasync16(Bbase + ch * CHUNKB + r * ROWPITCH + c4 * 16,
                      (const char*)&g_f16[(bR + r) * D + col] + c4 * 16);
        }
    }
}

__global__ void __launch_bounds__(256, 2) sim_mma_kernel()
{
    extern __shared__ char dsm[];
    __shared__ int labA[2][128];
    __shared__ int labB[2][128];

    const uint32_t smBase = smem_u32(dsm);
    const uint32_t Abase  = smBase;
    const uint32_t Bbase  = smBase + A_BYTES;
    const int tid  = threadIdx.x;
    const int warp = tid >> 5;
    const int lane = tid & 31;
    const int warpRow = warp >> 1;
    const int warpCol = warp & 1;
    const int g   = lane >> 2;
    const int tig = lane & 3;

    uint32_t aOff[2];
    #pragma unroll
    for (int mi = 0; mi < 2; mi++)
        aOff[mi] = (uint32_t)((warpRow * 32 + mi * 16 + (lane & 15)) * ROWPITCH
                              + ((lane >> 4) * 16));
    uint32_t bOff[4];
    #pragma unroll
    for (int nt = 0; nt < 4; nt++)
        bOff[nt] = (uint32_t)((warpCol * 64 + nt * 16 + (lane & 7) + ((lane & 16) ? 8 : 0))
                              * ROWPITCH + ((lane & 8) ? 16 : 0));

    // contiguous run: 2080 = 296*7 + 8
    const int cta   = blockIdx.x;
    const int cnt   = 7 + (cta < 8 ? 1 : 0);
    const int start = cta * 7 + min(cta, 8);

    int i, j;
    decode_tile(start, i, j);
    int aR = i * 128, bR = j * 128;

    // prologue: resident A (group), then first pair (chunks 0,1)
    load_A(Abase, aR, tid);
    cp_commit();
    load_B_pair(Bbase, 0, bR, tid);
    cp_commit();

    #pragma unroll 1
    for (int t = 0; t < cnt; t++) {
        const bool diag = (i == j);
        const bool hasNext = (t + 1 < cnt);
        int i_n = i, j_n = j + 1;
        if (j == NT - 1) { i_n = i + 1; j_n = i_n; }
        const bool iChange = hasNext && (i_n != i);
        const int bRn = j_n * 128;
        const int lb = t & 1;

        float acc[2][8][4];
        #pragma unroll
        for (int a = 0; a < 2; a++)
            #pragma unroll
            for (int b = 0; b < 8; b++)
                #pragma unroll
                for (int k = 0; k < 4; k++) acc[a][b][k] = 0.0f;

        #pragma unroll
        for (int half = 0; half < 2; half++) {
            cp_wait<0>();
            __syncthreads();

            if (half == 0 && tid < 128) {
                labA[lb][tid] = g_lab[aR + tid];
                labB[lb][tid] = g_lab[bR + tid];
            }

            // prefetch one pair ahead
            if (half == 0)
                load_B_pair(Bbase, 2, bR, tid);          // this tile's chunks 2,3
            else if (hasNext)
                load_B_pair(Bbase, 0, bRn, tid);         // next tile's chunks 0,1
            cp_commit();

            #pragma unroll
            for (int cc = 0; cc < 2; cc++) {
                const int c = half * 2 + cc;
                const uint32_t aS = Abase + c * CHUNKB;
                const uint32_t bS = Bbase + c * CHUNKB;
                #pragma unroll
                for (int k16 = 0; k16 < 2; k16++) {
                    uint32_t a[2][4];
                    ldmx4(a[0], aS + aOff[0] + k16 * 32);
                    ldmx4(a[1], aS + aOff[1] + k16 * 32);
                    uint32_t b[4][4];
                    #pragma unroll
                    for (int nt = 0; nt < 4; nt++)
                        ldmx4(b[nt], bS + bOff[nt] + k16 * 32);
                    #pragma unroll
                    for (int mi = 0; mi < 2; mi++)
                        #pragma unroll
                        for (int n8 = 0; n8 < 8; n8++) {
                            const uint32_t* bf = b[n8 >> 1];
                            if (n8 & 1) mma16816(acc[mi][n8], a[mi], bf[2], bf[3]);
                            else        mma16816(acc[mi][n8], a[mi], bf[0], bf[1]);
                        }
                }
            }
        }

        // on row-block change: prefetch new resident A during the epilogue
        if (iChange) {
            __syncthreads();              // all warps done reading old A
            load_A(Abase, i_n * 128, tid);
            cp_commit();
        }

        // ---------------- fused epilogue (row + column sums) ----------------
        float colPos[16], colNeg[16];
        #pragma unroll
        for (int x = 0; x < 16; x++) { colPos[x] = 0.0f; colNeg[x] = 0.0f; }

        #pragma unroll
        for (int mi = 0; mi < 2; mi++) {
            #pragma unroll
            for (int h = 0; h < 2; h++) {
                const int rT   = warpRow * 32 + mi * 16 + h * 8 + g;
                const int lrow = labA[lb][rT];
                float rowPos = 0.0f, rowNeg = 0.0f;
                #pragma unroll
                for (int n8 = 0; n8 < 8; n8++) {
                    #pragma unroll
                    for (int e = 0; e < 2; e++) {
                        const int cT = warpCol * 64 + n8 * 8 + 2 * tig + e;
                        float exv = ex2(fminf(acc[mi][n8][h * 2 + e], CLIP2));
                        if (diag) exv = (rT == cT) ? 0.0f : exv;
                        bool m = (lrow == labB[lb][cT]);
                        rowNeg += exv;
                        rowPos += m ? exv : 0.0f;
                        if (!diag) {
                            colNeg[n8 * 2 + e] += exv;
                            colPos[n8 * 2 + e] += m ? exv : 0.0f;
                        }
                    }
                }
                #pragma unroll
                for (int o = 1; o < 4; o <<= 1) {
                    rowPos += __shfl_xor_sync(0xffffffffu, rowPos, o);
                    rowNeg += __shfl_xor_sync(0xffffffffu, rowNeg, o);
                }
                if (tig == 0) {
                    atomicAdd(&g_pos[aR + rT], rowPos);
                    atomicAdd(&g_neg[aR + rT], rowNeg);
                }
            }
        }

        if (!diag) {
            #pragma unroll
            for (int x = 0; x < 16; x++) {
                #pragma unroll
                for (int o = 4; o < 32; o <<= 1) {
                    colPos[x] += __shfl_xor_sync(0xffffffffu, colPos[x], o);
                    colNeg[x] += __shfl_xor_sync(0xffffffffu, colNeg[x], o);
                }
            }
            if (g == 0) {
                #pragma unroll
                for (int x = 0; x < 16; x++) {
                    const int cT = warpCol * 64 + (x >> 1) * 8 + 2 * tig + (x & 1);
                    atomicAdd(&g_pos[bR + cT], colPos[x]);
                    atomicAdd(&g_neg[bR + cT], colNeg[x]);
                }
            }
        }

        i = i_n; j = j_n; aR = i * 128; bR = j * 128;
    }
}

// ---------------------------------------------------------------------------
// Kernel 3: final loss reduction (lg2.approx).
// ---------------------------------------------------------------------------
__global__ void __launch_bounds__(1024) loss_kernel(float* __restrict__ out)
{
    int t = threadIdx.x;
    float s = 0.0f;
    for (int idx = t; idx < NROWS; idx += 1024) {
        float p = fmaxf(g_pos[idx], 1e-8f);
        float n = fmaxf(g_neg[idx], 1e-8f);
        s += lg2(n) - lg2(p);
    }
    __shared__ float red[1024];
    red[t] = s;
    __syncthreads();
    #pragma unroll
    for (int o = 512; o > 0; o >>= 1) {
        if (t < o) red[t] += red[t + o];
        __syncthreads();
    }
    if (t == 0) out[0] = red[0] * (0.69314718056f / (float)NROWS);
}

// ---------------------------------------------------------------------------
extern "C" void kernel_launch(void* const* d_in, const int* in_sizes, int n_in,
                              void* d_out, int out_size)
{
    const float* feat  = (const float*)d_in[0];
    const int*   lab32 = (const int*)d_in[1];
    float*       out   = (float*)d_out;

    static bool attr_set = false;
    if (!attr_set) {
        cudaFuncSetAttribute(sim_mma_kernel, cudaFuncAttributeMaxDynamicSharedMemorySize,
                             SMEM_DYN_BYTES);
        attr_set = true;
    }

    normalize_kernel<<<NROWS / 8, 256>>>(feat, lab32);
    sim_mma_kernel<<<GRID, 256, SMEM_DYN_BYTES>>>();
    loss_kernel<<<1, 1024>>>(out);
}

// round 13
// speedup vs baseline: 1.5354x; 1.0773x over previous
#include <cuda_runtime.h>
#include <cuda_bf16.h>
#include <cstdint>
#include <math.h>

#define NROWS 8192
#define D     128
// alpha = sqrt((1/0.07) * log2(e))
#define ALPHA  4.539816f
#define CLIP2  14.4269504089f   // 10 * log2(e)

#define NT       64
#define NTILES   2080          // NT*(NT+1)/2
#define GRID     296           // 2 persistent CTAs per SM
#define ROWPITCH 80            // 64B data + 16B pad (LDSM conflict-free)
#define CHUNKB   (128 * ROWPITCH)          // 10240 per 32-col chunk
#define A_BYTES  (4 * CHUNKB)
#define B_BYTES  (4 * CHUNKB)
#define SMEM_DYN_BYTES (A_BYTES + B_BYTES) // 81920

// ---------------- device scratch -------------------------------------------
__device__ __nv_bfloat16 g_f16[NROWS * D];   // alpha-prescaled normalized rows
__device__ float g_pos[NROWS];
__device__ float g_neg[NROWS];
__device__ int   g_lab[NROWS];

// ---------------- helpers ---------------------------------------------------
__device__ __forceinline__ uint32_t smem_u32(const void* p) {
    return (uint32_t)__cvta_generic_to_shared(p);
}
__device__ __forceinline__ void cpasync16(uint32_t s, const void* g) {
    asm volatile("cp.async.cg.shared.global [%0], [%1], 16;" :: "r"(s), "l"(g));
}
__device__ __forceinline__ void cp_commit() {
    asm volatile("cp.async.commit_group;" ::: "memory");
}
template <int N>
__device__ __forceinline__ void cp_wait() {
    asm volatile("cp.async.wait_group %0;" :: "n"(N) : "memory");
}
__device__ __forceinline__ void ldmx4(uint32_t* r, uint32_t addr) {
    asm volatile("ldmatrix.sync.aligned.m8n8.x4.shared.b16 {%0,%1,%2,%3}, [%4];"
                 : "=r"(r[0]), "=r"(r[1]), "=r"(r[2]), "=r"(r[3]) : "r"(addr));
}
__device__ __forceinline__ void mma16816(float* c, const uint32_t* a, uint32_t b0, uint32_t b1) {
    asm volatile(
        "mma.sync.aligned.m16n8k16.row.col.f32.bf16.bf16.f32 "
        "{%0,%1,%2,%3}, {%4,%5,%6,%7}, {%8,%9}, {%0,%1,%2,%3};"
        : "+f"(c[0]), "+f"(c[1]), "+f"(c[2]), "+f"(c[3])
        : "r"(a[0]), "r"(a[1]), "r"(a[2]), "r"(a[3]), "r"(b0), "r"(b1));
}
__device__ __forceinline__ float ex2(float x) {
    float r;
    asm("ex2.approx.f32 %0, %1;" : "=f"(r) : "f"(x));
    return r;
}
__device__ __forceinline__ float lg2(float x) {
    float r;
    asm("lg2.approx.f32 %0, %1;" : "=f"(r) : "f"(x));
    return r;
}
__device__ __forceinline__ void decode_tile(int ti, int& i, int& j) {
    i = (int)floorf((129.0f - sqrtf(129.0f * 129.0f - 8.0f * (float)ti)) * 0.5f);
    while (i > 0 && ti < i * NT - i * (i - 1) / 2) --i;
    while (ti >= (i + 1) * NT - (i + 1) * i / 2) ++i;
    j = i + (ti - (i * NT - i * (i - 1) / 2));
}

// ---------------------------------------------------------------------------
// Kernel 1: 16 lanes per row, 32 rows per 512-thread block (2 waves total).
// Label dtype detection hoisted to one thread per block. Zeroes out[0].
// ---------------------------------------------------------------------------
__global__ void __launch_bounds__(512) normalize_kernel(
    const float* __restrict__ feat,
    const int*   __restrict__ lab32,
    float*       __restrict__ out)
{
    __shared__ int s_is64;
    const int tid  = threadIdx.x;
    const int sub  = tid >> 4;           // row within block 0..31
    const int l16  = tid & 15;           // lane within row group
    const int row  = blockIdx.x * 32 + sub;

    if (tid == 0) {
        bool is64 = true;
        #pragma unroll 8
        for (int i = 0; i < 32; i++)
            if (lab32[2 * i + 1] != 0) { is64 = false; break; }
        s_is64 = is64 ? 1 : 0;
        if (blockIdx.x == 0) out[0] = 0.0f;
    }

    float4 v0 = *(const float4*)&feat[row * D + l16 * 8];
    float4 v1 = *(const float4*)&feat[row * D + l16 * 8 + 4];

    float ss = v0.x * v0.x + v0.y * v0.y + v0.z * v0.z + v0.w * v0.w
             + v1.x * v1.x + v1.y * v1.y + v1.z * v1.z + v1.w * v1.w;
    #pragma unroll
    for (int o = 8; o > 0; o >>= 1) ss += __shfl_xor_sync(0xffffffffu, ss, o);
    float inv = ALPHA / fmaxf(sqrtf(ss), 1e-8f);

    ushort h[8];
    h[0] = __bfloat16_as_ushort(__float2bfloat16_rn(v0.x * inv));
    h[1] = __bfloat16_as_ushort(__float2bfloat16_rn(v0.y * inv));
    h[2] = __bfloat16_as_ushort(__float2bfloat16_rn(v0.z * inv));
    h[3] = __bfloat16_as_ushort(__float2bfloat16_rn(v0.w * inv));
    h[4] = __bfloat16_as_ushort(__float2bfloat16_rn(v1.x * inv));
    h[5] = __bfloat16_as_ushort(__float2bfloat16_rn(v1.y * inv));
    h[6] = __bfloat16_as_ushort(__float2bfloat16_rn(v1.z * inv));
    h[7] = __bfloat16_as_ushort(__float2bfloat16_rn(v1.w * inv));
    uint4 pk;
    pk.x = h[0] | (uint32_t)h[1] << 16;
    pk.y = h[2] | (uint32_t)h[3] << 16;
    pk.z = h[4] | (uint32_t)h[5] << 16;
    pk.w = h[6] | (uint32_t)h[7] << 16;
    *(uint4*)&((ushort*)g_f16)[row * D + l16 * 8] = pk;

    __syncthreads();
    if (l16 == 0) {
        g_pos[row] = 0.0f;
        g_neg[row] = 0.0f;
        g_lab[row] = s_is64 ? lab32[2 * row] : lab32[row];
    }
}

// ---------------------------------------------------------------------------
// Kernel 2: persistent CTAs over contiguous triangular tile runs; resident A;
// B streamed in 2-chunk pairs (one wait+sync per pair, prefetch 1 pair ahead).
// ---------------------------------------------------------------------------
__device__ __forceinline__ void load_A(uint32_t Abase, int aR, int tid) {
    #pragma unroll
    for (int ch = 0; ch < 4; ch++) {
        const int col = ch * 32;
        #pragma unroll
        for (int it = 0; it < 2; it++) {
            int idx = tid + it * 256;
            int r   = idx >> 2;
            int c4  = idx & 3;
            cpasync16(Abase + ch * CHUNKB + r * ROWPITCH + c4 * 16,
                      (const char*)&g_f16[(aR + r) * D + col] + c4 * 16);
        }
    }
}
__device__ __forceinline__ void load_B_pair(uint32_t Bbase, int c0, int bR, int tid) {
    #pragma unroll
    for (int cc = 0; cc < 2; cc++) {
        const int ch  = c0 + cc;
        const int col = ch * 32;
        #pragma unroll
        for (int it = 0; it < 2; it++) {
            int idx = tid + it * 256;
            int r   = idx >> 2;
            int c4  = idx & 3;
            cpasync16(Bbase + ch * CHUNKB + r * ROWPITCH + c4 * 16,
                      (const char*)&g_f16[(bR + r) * D + col] + c4 * 16);
        }
    }
}

__global__ void __launch_bounds__(256, 2) sim_mma_kernel()
{
    extern __shared__ char dsm[];
    __shared__ int labA[2][128];
    __shared__ int labB[2][128];

    const uint32_t smBase = smem_u32(dsm);
    const uint32_t Abase  = smBase;
    const uint32_t Bbase  = smBase + A_BYTES;
    const int tid  = threadIdx.x;
    const int warp = tid >> 5;
    const int lane = tid & 31;
    const int warpRow = warp >> 1;
    const int warpCol = warp & 1;
    const int g   = lane >> 2;
    const int tig = lane & 3;

    uint32_t aOff[2];
    #pragma unroll
    for (int mi = 0; mi < 2; mi++)
        aOff[mi] = (uint32_t)((warpRow * 32 + mi * 16 + (lane & 15)) * ROWPITCH
                              + ((lane >> 4) * 16));
    uint32_t bOff[4];
    #pragma unroll
    for (int nt = 0; nt < 4; nt++)
        bOff[nt] = (uint32_t)((warpCol * 64 + nt * 16 + (lane & 7) + ((lane & 16) ? 8 : 0))
                              * ROWPITCH + ((lane & 8) ? 16 : 0));

    const int cta   = blockIdx.x;
    const int cnt   = 7 + (cta < 8 ? 1 : 0);
    const int start = cta * 7 + min(cta, 8);

    int i, j;
    decode_tile(start, i, j);
    int aR = i * 128, bR = j * 128;

    load_A(Abase, aR, tid);
    cp_commit();
    load_B_pair(Bbase, 0, bR, tid);
    cp_commit();

    #pragma unroll 1
    for (int t = 0; t < cnt; t++) {
        const bool diag = (i == j);
        const bool hasNext = (t + 1 < cnt);
        int i_n = i, j_n = j + 1;
        if (j == NT - 1) { i_n = i + 1; j_n = i_n; }
        const bool iChange = hasNext && (i_n != i);
        const int bRn = j_n * 128;
        const int lb = t & 1;

        float acc[2][8][4];
        #pragma unroll
        for (int a = 0; a < 2; a++)
            #pragma unroll
            for (int b = 0; b < 8; b++)
                #pragma unroll
                for (int k = 0; k < 4; k++) acc[a][b][k] = 0.0f;

        #pragma unroll
        for (int half = 0; half < 2; half++) {
            cp_wait<0>();
            __syncthreads();

            if (half == 0 && tid < 128) {
                labA[lb][tid] = g_lab[aR + tid];
                labB[lb][tid] = g_lab[bR + tid];
            }

            if (half == 0)
                load_B_pair(Bbase, 2, bR, tid);
            else if (hasNext)
                load_B_pair(Bbase, 0, bRn, tid);
            cp_commit();

            #pragma unroll
            for (int cc = 0; cc < 2; cc++) {
                const int c = half * 2 + cc;
                const uint32_t aS = Abase + c * CHUNKB;
                const uint32_t bS = Bbase + c * CHUNKB;
                #pragma unroll
                for (int k16 = 0; k16 < 2; k16++) {
                    uint32_t a[2][4];
                    ldmx4(a[0], aS + aOff[0] + k16 * 32);
                    ldmx4(a[1], aS + aOff[1] + k16 * 32);
                    uint32_t b[4][4];
                    #pragma unroll
                    for (int nt = 0; nt < 4; nt++)
                        ldmx4(b[nt], bS + bOff[nt] + k16 * 32);
                    #pragma unroll
                    for (int mi = 0; mi < 2; mi++)
                        #pragma unroll
                        for (int n8 = 0; n8 < 8; n8++) {
                            const uint32_t* bf = b[n8 >> 1];
                            if (n8 & 1) mma16816(acc[mi][n8], a[mi], bf[2], bf[3]);
                            else        mma16816(acc[mi][n8], a[mi], bf[0], bf[1]);
                        }
                }
            }
        }

        if (iChange) {
            __syncthreads();
            load_A(Abase, i_n * 128, tid);
            cp_commit();
        }

        // ---------------- fused epilogue (row + column sums) ----------------
        float colPos[16], colNeg[16];
        #pragma unroll
        for (int x = 0; x < 16; x++) { colPos[x] = 0.0f; colNeg[x] = 0.0f; }

        #pragma unroll
        for (int mi = 0; mi < 2; mi++) {
            #pragma unroll
            for (int h = 0; h < 2; h++) {
                const int rT   = warpRow * 32 + mi * 16 + h * 8 + g;
                const int lrow = labA[lb][rT];
                float rowPos = 0.0f, rowNeg = 0.0f;
                #pragma unroll
                for (int n8 = 0; n8 < 8; n8++) {
                    #pragma unroll
                    for (int e = 0; e < 2; e++) {
                        const int cT = warpCol * 64 + n8 * 8 + 2 * tig + e;
                        float exv = ex2(fminf(acc[mi][n8][h * 2 + e], CLIP2));
                        if (diag) exv = (rT == cT) ? 0.0f : exv;
                        bool m = (lrow == labB[lb][cT]);
                        rowNeg += exv;
                        rowPos += m ? exv : 0.0f;
                        if (!diag) {
                            colNeg[n8 * 2 + e] += exv;
                            colPos[n8 * 2 + e] += m ? exv : 0.0f;
                        }
                    }
                }
                #pragma unroll
                for (int o = 1; o < 4; o <<= 1) {
                    rowPos += __shfl_xor_sync(0xffffffffu, rowPos, o);
                    rowNeg += __shfl_xor_sync(0xffffffffu, rowNeg, o);
                }
                if (tig == 0) {
                    atomicAdd(&g_pos[aR + rT], rowPos);
                    atomicAdd(&g_neg[aR + rT], rowNeg);
                }
            }
        }

        if (!diag) {
            #pragma unroll
            for (int x = 0; x < 16; x++) {
                #pragma unroll
                for (int o = 4; o < 32; o <<= 1) {
                    colPos[x] += __shfl_xor_sync(0xffffffffu, colPos[x], o);
                    colNeg[x] += __shfl_xor_sync(0xffffffffu, colNeg[x], o);
                }
            }
            if (g == 0) {
                #pragma unroll
                for (int x = 0; x < 16; x++) {
                    const int cT = warpCol * 64 + (x >> 1) * 8 + 2 * tig + (x & 1);
                    atomicAdd(&g_pos[bR + cT], colPos[x]);
                    atomicAdd(&g_neg[bR + cT], colNeg[x]);
                }
            }
        }

        i = i_n; j = j_n; aR = i * 128; bR = j * 128;
    }
}

// ---------------------------------------------------------------------------
// Kernel 3: loss reduction, 32 blocks, atomic accumulate into out[0].
// ---------------------------------------------------------------------------
__global__ void __launch_bounds__(256) loss_kernel(float* __restrict__ out)
{
    const int tid = threadIdx.x;
    const int idx = blockIdx.x * 256 + tid;
    float p = fmaxf(g_pos[idx], 1e-8f);
    float n = fmaxf(g_neg[idx], 1e-8f);
    float s = lg2(n) - lg2(p);
    #pragma unroll
    for (int o = 16; o > 0; o >>= 1) s += __shfl_xor_sync(0xffffffffu, s, o);
    __shared__ float red[8];
    if ((tid & 31) == 0) red[tid >> 5] = s;
    __syncthreads();
    if (tid == 0) {
        float tot = red[0] + red[1] + red[2] + red[3]
                  + red[4] + red[5] + red[6] + red[7];
        atomicAdd(out, tot * (0.69314718056f / (float)NROWS));
    }
}

// ---------------------------------------------------------------------------
extern "C" void kernel_launch(void* const* d_in, const int* in_sizes, int n_in,
                              void* d_out, int out_size)
{
    const float* feat  = (const float*)d_in[0];
    const int*   lab32 = (const int*)d_in[1];
    float*       out   = (float*)d_out;

    static bool attr_set = false;
    if (!attr_set) {
        cudaFuncSetAttribute(sim_mma_kernel, cudaFuncAttributeMaxDynamicSharedMemorySize,
                             SMEM_DYN_BYTES);
        attr_set = true;
    }

    normalize_kernel<<<NROWS / 32, 512>>>(feat, lab32, out);
    sim_mma_kernel<<<GRID, 256, SMEM_DYN_BYTES>>>();
    loss_kernel<<<NROWS / 256, 256>>>(out);
}